// round 7
// baseline (speedup 1.0000x reference)
#include <cuda_runtime.h>
#include <cuda_bf16.h>
#include <cstdint>
#include <math.h>

// GELU(x @ W^T + b). Pass 1: split f32 -> bf16 hi/lo global scratch.
// Pass 2: 3-term (hh+hl+lh) HMMA GEMM, 3-stage cp.async, 1 sync/iter, fused GELU.

#define GN   8192
#define GK   512
#define GOUT 512
#define BM   128
#define BN   64
#define KC   32
#define NIT  (GK / KC)          // 16
#define NST  3                  // pipeline stages
#define LDT  40                 // smem row stride in bf16 (80 B)
#define A_PART (BM * LDT * 2)   // 10240 B per A part (hi or lo)
#define B_PART (BN * LDT * 2)   // 5120 B
#define STAGE_B (2 * A_PART + 2 * B_PART)   // 30720 B
#define SMEM_B  (NST * STAGE_B)             // 92160 B
#define OFF_AHI 0
#define OFF_ALO A_PART
#define OFF_BHI (2 * A_PART)
#define OFF_BLO (2 * A_PART + B_PART)

#define XN (GN * GK)
#define WN (GOUT * GK)

__device__ __nv_bfloat16 g_Xhi[XN];
__device__ __nv_bfloat16 g_Xlo[XN];
__device__ __nv_bfloat16 g_Whi[WN];
__device__ __nv_bfloat16 g_Wlo[WN];

__device__ __forceinline__ uint32_t smem_u32(const void* p) {
    return (uint32_t)__cvta_generic_to_shared(p);
}
__device__ __forceinline__ void ldmx4(uint32_t* r, uint32_t addr) {
    asm volatile("ldmatrix.sync.aligned.m8n8.x4.shared.b16 {%0,%1,%2,%3}, [%4];"
                 : "=r"(r[0]), "=r"(r[1]), "=r"(r[2]), "=r"(r[3]) : "r"(addr));
}
__device__ __forceinline__ void mma16816(float* c, const uint32_t* a, const uint32_t* b) {
    asm volatile(
        "mma.sync.aligned.m16n8k16.row.col.f32.bf16.bf16.f32 "
        "{%0,%1,%2,%3}, {%4,%5,%6,%7}, {%8,%9}, {%0,%1,%2,%3};"
        : "+f"(c[0]), "+f"(c[1]), "+f"(c[2]), "+f"(c[3])
        : "r"(a[0]), "r"(a[1]), "r"(a[2]), "r"(a[3]), "r"(b[0]), "r"(b[1]));
}
__device__ __forceinline__ void cpasync16(uint32_t dst, const void* src) {
    asm volatile("cp.async.cg.shared.global [%0], [%1], 16;"
                 :: "r"(dst), "l"(src) : "memory");
}
__device__ __forceinline__ void cp_commit() {
    asm volatile("cp.async.commit_group;" ::: "memory");
}
__device__ __forceinline__ void cp_wait1() {
    asm volatile("cp.async.wait_group 1;" ::: "memory");
}
__device__ __forceinline__ void cp_wait0() {
    asm volatile("cp.async.wait_group 0;" ::: "memory");
}
__device__ __forceinline__ void split4(float4 v, uint2& hv, uint2& lv) {
    __nv_bfloat16 h0 = __float2bfloat16(v.x);
    __nv_bfloat16 h1 = __float2bfloat16(v.y);
    __nv_bfloat16 h2 = __float2bfloat16(v.z);
    __nv_bfloat16 h3 = __float2bfloat16(v.w);
    __nv_bfloat16 l0 = __float2bfloat16(v.x - __bfloat162float(h0));
    __nv_bfloat16 l1 = __float2bfloat16(v.y - __bfloat162float(h1));
    __nv_bfloat16 l2 = __float2bfloat16(v.z - __bfloat162float(h2));
    __nv_bfloat16 l3 = __float2bfloat16(v.w - __bfloat162float(h3));
    __nv_bfloat162 hp0(h0, h1), hp1(h2, h3), lp0(l0, l1), lp1(l2, l3);
    hv = make_uint2(*reinterpret_cast<uint32_t*>(&hp0), *reinterpret_cast<uint32_t*>(&hp1));
    lv = make_uint2(*reinterpret_cast<uint32_t*>(&lp0), *reinterpret_cast<uint32_t*>(&lp1));
}

// ---------------- pass 1: f32 -> bf16 hi/lo ----------------
__global__ __launch_bounds__(256)
void convert_kernel(const float* __restrict__ X, const float* __restrict__ W) {
    const int i = blockIdx.x * 256 + threadIdx.x;
    const int nx4 = XN / 4;
    uint2 hv, lv;
    if (i < nx4) {
        float4 v = reinterpret_cast<const float4*>(X)[i];
        split4(v, hv, lv);
        reinterpret_cast<uint2*>(g_Xhi)[i] = hv;
        reinterpret_cast<uint2*>(g_Xlo)[i] = lv;
    } else {
        const int j = i - nx4;
        if (j < WN / 4) {
            float4 v = reinterpret_cast<const float4*>(W)[j];
            split4(v, hv, lv);
            reinterpret_cast<uint2*>(g_Whi)[j] = hv;
            reinterpret_cast<uint2*>(g_Wlo)[j] = lv;
        }
    }
}

// ---------------- pass 2: HMMA GEMM + GELU ----------------
__global__ __launch_bounds__(256, 2)
void gemm_bf16x3_gelu(const float* __restrict__ bias, float* __restrict__ out) {
    extern __shared__ char sm[];
    const uint32_t smem_base = smem_u32(sm);

    const int tid = threadIdx.x;
    const int wid = tid >> 5;
    const int lid = tid & 31;
    const int col0 = blockIdx.x * BN;
    const int row0 = blockIdx.y * BM;

    const int m0 = (wid >> 1) * 32;   // 4 warps along M
    const int n0 = (wid & 1) * 32;    // 2 warps along N
    const int lrow  = lid & 15;
    const int lkoff = (lid >> 4) * 8;

    // ---- cp.async thread mapping ----
    // A parts: 512 16B-chunks (128 rows x 4); this thread does chunks tid, tid+256.
    // B parts: 256 chunks (64 rows x 4); this thread does chunk tid.
    const int arA0 = tid >> 2,        acA0 = tid & 3;
    const int arA1 = (tid + 256) >> 2, acA1 = (tid + 256) & 3;
    const int arB  = tid >> 2,        acB  = tid & 3;

    // gmem pointers (advance by KC per issued stage)
    const __nv_bfloat16* pXh0 = g_Xhi + (size_t)(row0 + arA0) * GK + acA0 * 8;
    const __nv_bfloat16* pXh1 = g_Xhi + (size_t)(row0 + arA1) * GK + acA1 * 8;
    const __nv_bfloat16* pXl0 = g_Xlo + (size_t)(row0 + arA0) * GK + acA0 * 8;
    const __nv_bfloat16* pXl1 = g_Xlo + (size_t)(row0 + arA1) * GK + acA1 * 8;
    const __nv_bfloat16* pWh  = g_Whi + (size_t)(col0 + arB) * GK + acB * 8;
    const __nv_bfloat16* pWl  = g_Wlo + (size_t)(col0 + arB) * GK + acB * 8;

    // smem destination offsets (within a stage)
    const uint32_t dA0 = OFF_AHI + (uint32_t)(arA0 * LDT * 2 + acA0 * 16);
    const uint32_t dA1 = OFF_AHI + (uint32_t)(arA1 * LDT * 2 + acA1 * 16);
    const uint32_t dB  = OFF_BHI + (uint32_t)(arB * LDT * 2 + acB * 16);

    // ldmatrix base addresses (within a stage)
    uint32_t aHiA[2], aLoA[2], bHiA[2], bLoA[2];
#pragma unroll
    for (int f = 0; f < 2; f++) {
        const uint32_t am = (uint32_t)((m0 + f * 16 + lrow) * LDT * 2);
        const uint32_t bn = (uint32_t)((n0 + f * 16 + lrow) * LDT * 2);
        aHiA[f] = smem_base + OFF_AHI + am;
        aLoA[f] = smem_base + OFF_ALO + am;
        bHiA[f] = smem_base + OFF_BHI + bn;
        bLoA[f] = smem_base + OFF_BLO + bn;
    }

    float acc[2][4][4];
#pragma unroll
    for (int mf = 0; mf < 2; mf++)
#pragma unroll
        for (int nf = 0; nf < 4; nf++)
#pragma unroll
            for (int q = 0; q < 4; q++) acc[mf][nf][q] = 0.0f;

    auto issue = [&](int slot) {
        const uint32_t so = smem_base + (uint32_t)slot * STAGE_B;
        cpasync16(so + dA0, pXh0);
        cpasync16(so + dA1, pXh1);
        cpasync16(so + dA0 + A_PART, pXl0);
        cpasync16(so + dA1 + A_PART, pXl1);
        cpasync16(so + dB, pWh);
        cpasync16(so + dB + B_PART, pWl);
        cp_commit();
        pXh0 += KC; pXh1 += KC; pXl0 += KC; pXl1 += KC; pWh += KC; pWl += KC;
    };

    issue(0);
    issue(1);

    int slot = 0;           // stage slot of current iteration
    int wslot = 2;          // slot next issue writes
    for (int it = 0; it < NIT; it++) {
        if (it == NIT - 1) cp_wait0(); else cp_wait1();
        __syncthreads();
        if (it + 2 < NIT) {
            issue(wslot);
            wslot = (wslot == NST - 1) ? 0 : wslot + 1;
        }

        const uint32_t sb = (uint32_t)slot * STAGE_B;
#pragma unroll
        for (int ks = 0; ks < 2; ks++) {
            const uint32_t kb = sb + (uint32_t)(ks * 16 + lkoff) * 2;
            uint32_t ah[2][4], al[2][4];
#pragma unroll
            for (int mf = 0; mf < 2; mf++) {
                ldmx4(ah[mf], aHiA[mf] + kb);
                ldmx4(al[mf], aLoA[mf] + kb);
            }
            uint32_t bh[4][2], bl[4][2];
#pragma unroll
            for (int f = 0; f < 2; f++) {
                uint32_t r4[4];
                ldmx4(r4, bHiA[f] + kb);
                bh[f * 2][0] = r4[0]; bh[f * 2 + 1][0] = r4[1];
                bh[f * 2][1] = r4[2]; bh[f * 2 + 1][1] = r4[3];
                ldmx4(r4, bLoA[f] + kb);
                bl[f * 2][0] = r4[0]; bl[f * 2 + 1][0] = r4[1];
                bl[f * 2][1] = r4[2]; bl[f * 2 + 1][1] = r4[3];
            }
#pragma unroll
            for (int mf = 0; mf < 2; mf++)
#pragma unroll
                for (int nf = 0; nf < 4; nf++) {
                    mma16816(acc[mf][nf], ah[mf], bh[nf]);
                    mma16816(acc[mf][nf], ah[mf], bl[nf]);
                    mma16816(acc[mf][nf], al[mf], bh[nf]);
                }
        }
        slot = (slot == NST - 1) ? 0 : slot + 1;
    }

    // ---- epilogue: +bias, exact GELU, store ----
    const float kInvSqrt2 = 0.70710678118654752440f;
    const int lr = lid >> 2;
    const int lc = (lid & 3) * 2;
#pragma unroll
    for (int mf = 0; mf < 2; mf++) {
#pragma unroll
        for (int nf = 0; nf < 4; nf++) {
            const int col = col0 + n0 + nf * 8 + lc;
            const float2 bv = *reinterpret_cast<const float2*>(bias + col);
            const int ra = row0 + m0 + mf * 16 + lr;
#pragma unroll
            for (int half = 0; half < 2; half++) {
                const int r = ra + half * 8;
                float v0 = acc[mf][nf][half * 2 + 0] + bv.x;
                float v1 = acc[mf][nf][half * 2 + 1] + bv.y;
                float g0 = 0.5f * v0 * (1.0f + erff(v0 * kInvSqrt2));
                float g1 = 0.5f * v1 * (1.0f + erff(v1 * kInvSqrt2));
                *reinterpret_cast<float2*>(out + (size_t)r * GOUT + col) =
                    make_float2(g0, g1);
            }
        }
    }
}

extern "C" void kernel_launch(void* const* d_in, const int* in_sizes, int n_in,
                              void* d_out, int out_size) {
    // metadata order: x, adj (unused), W, b, a (unused)
    const float* X    = (const float*)d_in[0];
    const float* W    = (const float*)d_in[2];
    const float* bias = (const float*)d_in[3];
    float* out        = (float*)d_out;

    const int total4 = XN / 4 + WN / 4;
    convert_kernel<<<(total4 + 255) / 256, 256>>>(X, W);

    static bool attr_set = false;
    if (!attr_set) {
        cudaFuncSetAttribute(gemm_bf16x3_gelu,
                             cudaFuncAttributeMaxDynamicSharedMemorySize, SMEM_B);
        attr_set = true;
    }
    dim3 grid(GOUT / BN, GN / BM);   // (8, 64) = 512 CTAs
    gemm_bf16x3_gelu<<<grid, 256, SMEM_B>>>(bias, out);
}

// round 8
// speedup vs baseline: 2.1064x; 2.1064x over previous
#include <cuda_runtime.h>
#include <cuda_fp16.h>
#include <cstdint>
#include <math.h>

// GELU(x @ W^T + b). Pass 1: f32 -> fp16 global scratch (X, W).
// Pass 2: single-pass fp16 HMMA GEMM (fp32 accum), 2-stage cp.async, fused GELU.

#define GN   8192
#define GK   512
#define GOUT 512
#define BM   128
#define BN   128
#define KC   32
#define NIT  (GK / KC)          // 16
#define LDT  40                 // smem row stride in fp16 (80 B)
#define A_PART (BM * LDT * 2)   // 10240 B
#define B_PART (BN * LDT * 2)   // 10240 B
#define STAGE_B (A_PART + B_PART)   // 20480 B
#define SMEM_B  (2 * STAGE_B)       // 40960 B (fits static smem)

#define XN (GN * GK)
#define WN (GOUT * GK)

__device__ __half g_Xh[XN];
__device__ __half g_Wh[WN];

__device__ __forceinline__ uint32_t smem_u32(const void* p) {
    return (uint32_t)__cvta_generic_to_shared(p);
}
__device__ __forceinline__ void ldmx4(uint32_t* r, uint32_t addr) {
    asm volatile("ldmatrix.sync.aligned.m8n8.x4.shared.b16 {%0,%1,%2,%3}, [%4];"
                 : "=r"(r[0]), "=r"(r[1]), "=r"(r[2]), "=r"(r[3]) : "r"(addr));
}
__device__ __forceinline__ void mma16816(float* c, const uint32_t* a, const uint32_t* b) {
    asm volatile(
        "mma.sync.aligned.m16n8k16.row.col.f32.f16.f16.f32 "
        "{%0,%1,%2,%3}, {%4,%5,%6,%7}, {%8,%9}, {%0,%1,%2,%3};"
        : "+f"(c[0]), "+f"(c[1]), "+f"(c[2]), "+f"(c[3])
        : "r"(a[0]), "r"(a[1]), "r"(a[2]), "r"(a[3]), "r"(b[0]), "r"(b[1]));
}
__device__ __forceinline__ void cpasync16(uint32_t dst, const void* src) {
    asm volatile("cp.async.cg.shared.global [%0], [%1], 16;"
                 :: "r"(dst), "l"(src) : "memory");
}
__device__ __forceinline__ void cp_commit() {
    asm volatile("cp.async.commit_group;" ::: "memory");
}
__device__ __forceinline__ void cp_wait1() {
    asm volatile("cp.async.wait_group 1;" ::: "memory");
}
__device__ __forceinline__ void cp_wait0() {
    asm volatile("cp.async.wait_group 0;" ::: "memory");
}

// ---------------- pass 1: f32 -> fp16 ----------------
__global__ __launch_bounds__(256)
void convert_kernel(const float* __restrict__ X, const float* __restrict__ W) {
    const int i = blockIdx.x * 256 + threadIdx.x;   // float4 index
    const int nx4 = XN / 4;
    if (i < nx4) {
        float4 v = reinterpret_cast<const float4*>(X)[i];
        __half2 p0 = __float22half2_rn(make_float2(v.x, v.y));
        __half2 p1 = __float22half2_rn(make_float2(v.z, v.w));
        reinterpret_cast<uint2*>(g_Xh)[i] =
            make_uint2(*reinterpret_cast<uint32_t*>(&p0), *reinterpret_cast<uint32_t*>(&p1));
    } else {
        const int j = i - nx4;
        if (j < WN / 4) {
            float4 v = reinterpret_cast<const float4*>(W)[j];
            __half2 p0 = __float22half2_rn(make_float2(v.x, v.y));
            __half2 p1 = __float22half2_rn(make_float2(v.z, v.w));
            reinterpret_cast<uint2*>(g_Wh)[j] =
                make_uint2(*reinterpret_cast<uint32_t*>(&p0), *reinterpret_cast<uint32_t*>(&p1));
        }
    }
}

// ---------------- pass 2: fp16 HMMA GEMM + GELU ----------------
__global__ __launch_bounds__(256, 2)
void gemm_f16_gelu(const float* __restrict__ bias, float* __restrict__ out) {
    __shared__ __align__(16) char sm[SMEM_B];
    const uint32_t smem_base = smem_u32(sm);

    const int tid = threadIdx.x;
    const int wid = tid >> 5;
    const int lid = tid & 31;
    const int col0 = blockIdx.x * BN;
    const int row0 = blockIdx.y * BM;

    const int m0 = (wid >> 1) * 32;   // 4 warps along M
    const int n0 = (wid & 1) * 64;    // 2 warps along N
    const int lrow  = lid & 15;
    const int lkoff = (lid >> 4) * 8;

    // cp.async mapping: 512 16B-chunks per part (128 rows x 4); thread does tid, tid+256.
    const int r0_ = tid >> 2,         c0_ = tid & 3;
    const int r1_ = (tid + 256) >> 2, c1_ = (tid + 256) & 3;

    // gmem pointers (advance by KC per issued stage)
    const __half* pX0 = g_Xh + (size_t)(row0 + r0_) * GK + c0_ * 8;
    const __half* pX1 = g_Xh + (size_t)(row0 + r1_) * GK + c1_ * 8;
    const __half* pW0 = g_Wh + (size_t)(col0 + r0_) * GK + c0_ * 8;
    const __half* pW1 = g_Wh + (size_t)(col0 + r1_) * GK + c1_ * 8;

    // smem destinations (within a stage)
    const uint32_t dA0 = (uint32_t)(r0_ * LDT * 2 + c0_ * 16);
    const uint32_t dA1 = (uint32_t)(r1_ * LDT * 2 + c1_ * 16);
    const uint32_t dB0 = A_PART + dA0;
    const uint32_t dB1 = A_PART + dA1;

    // ldmatrix base addresses (within a stage)
    uint32_t aA[2], bA[4];
#pragma unroll
    for (int f = 0; f < 2; f++)
        aA[f] = smem_base + (uint32_t)((m0 + f * 16 + lrow) * LDT * 2);
#pragma unroll
    for (int f = 0; f < 4; f++)
        bA[f] = smem_base + A_PART + (uint32_t)((n0 + f * 16 + lrow) * LDT * 2);

    float acc[2][8][4];
#pragma unroll
    for (int mf = 0; mf < 2; mf++)
#pragma unroll
        for (int nf = 0; nf < 8; nf++)
#pragma unroll
            for (int q = 0; q < 4; q++) acc[mf][nf][q] = 0.0f;

    auto issue = [&](int slot) {
        const uint32_t so = smem_base + (uint32_t)slot * STAGE_B;
        cpasync16(so + dA0, pX0);
        cpasync16(so + dA1, pX1);
        cpasync16(so + dB0, pW0);
        cpasync16(so + dB1, pW1);
        cp_commit();
        pX0 += KC; pX1 += KC; pW0 += KC; pW1 += KC;
    };

    issue(0);
    issue(1);

    for (int it = 0; it < NIT; it++) {
        const int st = it & 1;
        const uint32_t sb = (uint32_t)st * STAGE_B;
        if (it == NIT - 1) cp_wait0(); else cp_wait1();
        __syncthreads();

#pragma unroll
        for (int ks = 0; ks < 2; ks++) {
            const uint32_t kb = sb + (uint32_t)(ks * 16 + lkoff) * 2;
            uint32_t a[2][4];
#pragma unroll
            for (int mf = 0; mf < 2; mf++) ldmx4(a[mf], aA[mf] + kb);
            uint32_t b[8][2];
#pragma unroll
            for (int f = 0; f < 4; f++) {
                uint32_t r4[4];
                ldmx4(r4, bA[f] + kb);
                b[f * 2][0] = r4[0]; b[f * 2 + 1][0] = r4[1];
                b[f * 2][1] = r4[2]; b[f * 2 + 1][1] = r4[3];
            }
#pragma unroll
            for (int mf = 0; mf < 2; mf++)
#pragma unroll
                for (int nf = 0; nf < 8; nf++)
                    mma16816(acc[mf][nf], a[mf], b[nf]);
        }
        __syncthreads();
        if (it + 2 < NIT) issue(st);
    }

    // ---- epilogue: +bias, exact GELU, store ----
    const float kInvSqrt2 = 0.70710678118654752440f;
    const int lr = lid >> 2;
    const int lc = (lid & 3) * 2;
#pragma unroll
    for (int mf = 0; mf < 2; mf++) {
#pragma unroll
        for (int nf = 0; nf < 8; nf++) {
            const int col = col0 + n0 + nf * 8 + lc;
            const float2 bv = *reinterpret_cast<const float2*>(bias + col);
            const int ra = row0 + m0 + mf * 16 + lr;
#pragma unroll
            for (int half_ = 0; half_ < 2; half_++) {
                const int r = ra + half_ * 8;
                float v0 = acc[mf][nf][half_ * 2 + 0] + bv.x;
                float v1 = acc[mf][nf][half_ * 2 + 1] + bv.y;
                float g0 = 0.5f * v0 * (1.0f + erff(v0 * kInvSqrt2));
                float g1 = 0.5f * v1 * (1.0f + erff(v1 * kInvSqrt2));
                *reinterpret_cast<float2*>(out + (size_t)r * GOUT + col) =
                    make_float2(g0, g1);
            }
        }
    }
}

extern "C" void kernel_launch(void* const* d_in, const int* in_sizes, int n_in,
                              void* d_out, int out_size) {
    // metadata order: x, adj (unused), W, b, a (unused)
    const float* X    = (const float*)d_in[0];
    const float* W    = (const float*)d_in[2];
    const float* bias = (const float*)d_in[3];
    float* out        = (float*)d_out;

    const int total4 = XN / 4 + WN / 4;
    convert_kernel<<<(total4 + 255) / 256, 256>>>(X, W);

    dim3 grid(GOUT / BN, GN / BM);   // (4, 64) = 256 CTAs
    gemm_f16_gelu<<<grid, 256>>>(bias, out);
}

// round 11
// speedup vs baseline: 2.1752x; 1.0326x over previous
#include <cuda_runtime.h>
#include <cuda_fp16.h>
#include <cstdint>
#include <math.h>

// GELU(x @ W^T + b). Pass 1: f32 -> fp16 global scratch (X, W).
// Pass 2: fp16 HMMA GEMM (fp32 accum), 3-stage cp.async, 1 sync/iter, fused GELU.

#define GN   8192
#define GK   512
#define GOUT 512
#define BM   128
#define BN   128
#define KC   32
#define NIT  (GK / KC)          // 16
#define NST  3
#define LDT  40                 // smem row stride in fp16 (80 B)
#define A_PART (BM * LDT * 2)   // 10240 B
#define B_PART (BN * LDT * 2)   // 10240 B
#define STAGE_B (A_PART + B_PART)   // 20480 B
#define SMEM_B  (NST * STAGE_B)     // 61440 B (dynamic)

#define XN (GN * GK)
#define WN (GOUT * GK)

__device__ __half g_Xh[XN];
__device__ __half g_Wh[WN];

__device__ __forceinline__ uint32_t smem_u32(const void* p) {
    return (uint32_t)__cvta_generic_to_shared(p);
}
__device__ __forceinline__ void ldmx4(uint32_t* r, uint32_t addr) {
    asm volatile("ldmatrix.sync.aligned.m8n8.x4.shared.b16 {%0,%1,%2,%3}, [%4];"
                 : "=r"(r[0]), "=r"(r[1]), "=r"(r[2]), "=r"(r[3]) : "r"(addr));
}
__device__ __forceinline__ void mma16816(float* c, const uint32_t* a, const uint32_t* b) {
    asm volatile(
        "mma.sync.aligned.m16n8k16.row.col.f32.f16.f16.f32 "
        "{%0,%1,%2,%3}, {%4,%5,%6,%7}, {%8,%9}, {%0,%1,%2,%3};"
        : "+f"(c[0]), "+f"(c[1]), "+f"(c[2]), "+f"(c[3])
        : "r"(a[0]), "r"(a[1]), "r"(a[2]), "r"(a[3]), "r"(b[0]), "r"(b[1]));
}
__device__ __forceinline__ void cpasync16(uint32_t dst, const void* src) {
    asm volatile("cp.async.cg.shared.global [%0], [%1], 16;"
                 :: "r"(dst), "l"(src) : "memory");
}
__device__ __forceinline__ void cp_commit() {
    asm volatile("cp.async.commit_group;" ::: "memory");
}
__device__ __forceinline__ void cp_wait1() {
    asm volatile("cp.async.wait_group 1;" ::: "memory");
}
__device__ __forceinline__ void cp_wait0() {
    asm volatile("cp.async.wait_group 0;" ::: "memory");
}

// ---------------- pass 1: f32 -> fp16 ----------------
__global__ __launch_bounds__(256)
void convert_kernel(const float* __restrict__ X, const float* __restrict__ W) {
    const int i = blockIdx.x * 256 + threadIdx.x;
    const int nx4 = XN / 4;
    if (i < nx4) {
        float4 v = reinterpret_cast<const float4*>(X)[i];
        __half2 p0 = __float22half2_rn(make_float2(v.x, v.y));
        __half2 p1 = __float22half2_rn(make_float2(v.z, v.w));
        reinterpret_cast<uint2*>(g_Xh)[i] =
            make_uint2(*reinterpret_cast<uint32_t*>(&p0), *reinterpret_cast<uint32_t*>(&p1));
    } else {
        const int j = i - nx4;
        if (j < WN / 4) {
            float4 v = reinterpret_cast<const float4*>(W)[j];
            __half2 p0 = __float22half2_rn(make_float2(v.x, v.y));
            __half2 p1 = __float22half2_rn(make_float2(v.z, v.w));
            reinterpret_cast<uint2*>(g_Wh)[j] =
                make_uint2(*reinterpret_cast<uint32_t*>(&p0), *reinterpret_cast<uint32_t*>(&p1));
        }
    }
}

// ---------------- pass 2: fp16 HMMA GEMM + GELU ----------------
__global__ __launch_bounds__(256, 2)
void gemm_f16_gelu(const float* __restrict__ bias, float* __restrict__ out) {
    extern __shared__ __align__(16) char sm[];
    const uint32_t smem_base = smem_u32(sm);

    const int tid = threadIdx.x;
    const int wid = tid >> 5;
    const int lid = tid & 31;
    const int col0 = blockIdx.x * BN;
    const int row0 = blockIdx.y * BM;

    const int m0 = (wid >> 1) * 32;   // 4 warps along M
    const int n0 = (wid & 1) * 64;    // 2 warps along N
    const int lrow  = lid & 15;
    const int lkoff = (lid >> 4) * 8;

    // cp.async mapping: 512 16B-chunks per part; thread does tid, tid+256.
    const int r0_ = tid >> 2,         c0_ = tid & 3;
    const int r1_ = (tid + 256) >> 2, c1_ = (tid + 256) & 3;

    const __half* pX0 = g_Xh + (size_t)(row0 + r0_) * GK + c0_ * 8;
    const __half* pX1 = g_Xh + (size_t)(row0 + r1_) * GK + c1_ * 8;
    const __half* pW0 = g_Wh + (size_t)(col0 + r0_) * GK + c0_ * 8;
    const __half* pW1 = g_Wh + (size_t)(col0 + r1_) * GK + c1_ * 8;

    const uint32_t dA0 = (uint32_t)(r0_ * LDT * 2 + c0_ * 16);
    const uint32_t dA1 = (uint32_t)(r1_ * LDT * 2 + c1_ * 16);
    const uint32_t dB0 = A_PART + dA0;
    const uint32_t dB1 = A_PART + dA1;

    uint32_t aA[2], bA[4];
#pragma unroll
    for (int f = 0; f < 2; f++)
        aA[f] = smem_base + (uint32_t)((m0 + f * 16 + lrow) * LDT * 2);
#pragma unroll
    for (int f = 0; f < 4; f++)
        bA[f] = smem_base + A_PART + (uint32_t)((n0 + f * 16 + lrow) * LDT * 2);

    float acc[2][8][4];
#pragma unroll
    for (int mf = 0; mf < 2; mf++)
#pragma unroll
        for (int nf = 0; nf < 8; nf++)
#pragma unroll
            for (int q = 0; q < 4; q++) acc[mf][nf][q] = 0.0f;

    auto issue = [&](int slot) {
        const uint32_t so = smem_base + (uint32_t)slot * STAGE_B;
        cpasync16(so + dA0, pX0);
        cpasync16(so + dA1, pX1);
        cpasync16(so + dB0, pW0);
        cpasync16(so + dB1, pW1);
        cp_commit();
        pX0 += KC; pX1 += KC; pW0 += KC; pW1 += KC;
    };

    issue(0);
    issue(1);

    int slot = 0;     // stage being computed
    int wslot = 2;    // stage next issue writes
    for (int it = 0; it < NIT; it++) {
        if (it == NIT - 1) cp_wait0(); else cp_wait1();
        __syncthreads();                        // all warps done with slot (it-1)%3
        if (it + 2 < NIT) {
            issue(wslot);                       // writes slot (it+2)%3 == (it-1)%3: safe
            wslot = (wslot == NST - 1) ? 0 : wslot + 1;
        }

        const uint32_t sb = (uint32_t)slot * STAGE_B;
#pragma unroll
        for (int ks = 0; ks < 2; ks++) {
            const uint32_t kb = sb + (uint32_t)(ks * 16 + lkoff) * 2;
            uint32_t a[2][4];
#pragma unroll
            for (int mf = 0; mf < 2; mf++) ldmx4(a[mf], aA[mf] + kb);
            uint32_t b[8][2];
#pragma unroll
            for (int f = 0; f < 4; f++) {
                uint32_t r4[4];
                ldmx4(r4, bA[f] + kb);
                b[f * 2][0] = r4[0]; b[f * 2 + 1][0] = r4[1];
                b[f * 2][1] = r4[2]; b[f * 2 + 1][1] = r4[3];
            }
#pragma unroll
            for (int mf = 0; mf < 2; mf++)
#pragma unroll
                for (int nf = 0; nf < 8; nf++)
                    mma16816(acc[mf][nf], a[mf], b[nf]);
        }
        slot = (slot == NST - 1) ? 0 : slot + 1;
    }

    // ---- epilogue: +bias, exact GELU, store ----
    const float kInvSqrt2 = 0.70710678118654752440f;
    const int lr = lid >> 2;
    const int lc = (lid & 3) * 2;
#pragma unroll
    for (int mf = 0; mf < 2; mf++) {
#pragma unroll
        for (int nf = 0; nf < 8; nf++) {
            const int col = col0 + n0 + nf * 8 + lc;
            const float2 bv = *reinterpret_cast<const float2*>(bias + col);
            const int ra = row0 + m0 + mf * 16 + lr;
#pragma unroll
            for (int half_ = 0; half_ < 2; half_++) {
                const int r = ra + half_ * 8;
                float v0 = acc[mf][nf][half_ * 2 + 0] + bv.x;
                float v1 = acc[mf][nf][half_ * 2 + 1] + bv.y;
                float g0 = 0.5f * v0 * (1.0f + erff(v0 * kInvSqrt2));
                float g1 = 0.5f * v1 * (1.0f + erff(v1 * kInvSqrt2));
                *reinterpret_cast<float2*>(out + (size_t)r * GOUT + col) =
                    make_float2(g0, g1);
            }
        }
    }
}

extern "C" void kernel_launch(void* const* d_in, const int* in_sizes, int n_in,
                              void* d_out, int out_size) {
    // metadata order: x, adj (unused), W, b, a (unused)
    const float* X    = (const float*)d_in[0];
    const float* W    = (const float*)d_in[2];
    const float* bias = (const float*)d_in[3];
    float* out        = (float*)d_out;

    const int total4 = XN / 4 + WN / 4;
    convert_kernel<<<(total4 + 255) / 256, 256>>>(X, W);

    static bool attr_set = false;
    if (!attr_set) {
        cudaFuncSetAttribute(gemm_f16_gelu,
                             cudaFuncAttributeMaxDynamicSharedMemorySize, SMEM_B);
        attr_set = true;
    }
    dim3 grid(GOUT / BN, GN / BM);   // (4, 64) = 256 CTAs
    gemm_f16_gelu<<<grid, 256, SMEM_B>>>(bias, out);
}

// round 16
// speedup vs baseline: 2.1943x; 1.0088x over previous
#include <cuda_runtime.h>
#include <cuda_fp16.h>
#include <cstdint>
#include <math.h>

// GELU(x @ W^T + b). Pass 1: f32 -> fp16 global scratch (X, W).
// Pass 2: fp16 HMMA GEMM (fp32 accum), 512-thr CTA (4x4 warps, 32x32 warp tile),
// 3-stage cp.async, 1 sync/iter, fused GELU.

#define GN   8192
#define GK   512
#define GOUT 512
#define BM   128
#define BN   128
#define KC   32
#define NIT  (GK / KC)          // 16
#define NST  3
#define LDT  40                 // smem row stride in fp16 (80 B)
#define A_PART (BM * LDT * 2)   // 10240 B
#define B_PART (BN * LDT * 2)   // 10240 B
#define STAGE_B (A_PART + B_PART)   // 20480 B
#define SMEM_B  (NST * STAGE_B)     // 61440 B (dynamic)

#define XN (GN * GK)
#define WN (GOUT * GK)

__device__ __half g_Xh[XN];
__device__ __half g_Wh[WN];

__device__ __forceinline__ uint32_t smem_u32(const void* p) {
    return (uint32_t)__cvta_generic_to_shared(p);
}
__device__ __forceinline__ void ldmx4(uint32_t* r, uint32_t addr) {
    asm volatile("ldmatrix.sync.aligned.m8n8.x4.shared.b16 {%0,%1,%2,%3}, [%4];"
                 : "=r"(r[0]), "=r"(r[1]), "=r"(r[2]), "=r"(r[3]) : "r"(addr));
}
__device__ __forceinline__ void mma16816(float* c, const uint32_t* a, const uint32_t* b) {
    asm volatile(
        "mma.sync.aligned.m16n8k16.row.col.f32.f16.f16.f32 "
        "{%0,%1,%2,%3}, {%4,%5,%6,%7}, {%8,%9}, {%0,%1,%2,%3};"
        : "+f"(c[0]), "+f"(c[1]), "+f"(c[2]), "+f"(c[3])
        : "r"(a[0]), "r"(a[1]), "r"(a[2]), "r"(a[3]), "r"(b[0]), "r"(b[1]));
}
__device__ __forceinline__ void cpasync16(uint32_t dst, const void* src) {
    asm volatile("cp.async.cg.shared.global [%0], [%1], 16;"
                 :: "r"(dst), "l"(src) : "memory");
}
__device__ __forceinline__ void cp_commit() {
    asm volatile("cp.async.commit_group;" ::: "memory");
}
__device__ __forceinline__ void cp_wait1() {
    asm volatile("cp.async.wait_group 1;" ::: "memory");
}
__device__ __forceinline__ void cp_wait0() {
    asm volatile("cp.async.wait_group 0;" ::: "memory");
}

// ---------------- pass 1: f32 -> fp16 ----------------
__global__ __launch_bounds__(256)
void convert_kernel(const float* __restrict__ X, const float* __restrict__ W) {
    const int i = blockIdx.x * 256 + threadIdx.x;
    const int nx4 = XN / 4;
    if (i < nx4) {
        float4 v = reinterpret_cast<const float4*>(X)[i];
        __half2 p0 = __float22half2_rn(make_float2(v.x, v.y));
        __half2 p1 = __float22half2_rn(make_float2(v.z, v.w));
        reinterpret_cast<uint2*>(g_Xh)[i] =
            make_uint2(*reinterpret_cast<uint32_t*>(&p0), *reinterpret_cast<uint32_t*>(&p1));
    } else {
        const int j = i - nx4;
        if (j < WN / 4) {
            float4 v = reinterpret_cast<const float4*>(W)[j];
            __half2 p0 = __float22half2_rn(make_float2(v.x, v.y));
            __half2 p1 = __float22half2_rn(make_float2(v.z, v.w));
            reinterpret_cast<uint2*>(g_Wh)[j] =
                make_uint2(*reinterpret_cast<uint32_t*>(&p0), *reinterpret_cast<uint32_t*>(&p1));
        }
    }
}

// ---------------- pass 2: fp16 HMMA GEMM + GELU ----------------
__global__ __launch_bounds__(512, 2)
void gemm_f16_gelu(const float* __restrict__ bias, float* __restrict__ out) {
    extern __shared__ __align__(16) char sm[];
    const uint32_t smem_base = smem_u32(sm);

    const int tid = threadIdx.x;
    const int wid = tid >> 5;
    const int lid = tid & 31;
    const int col0 = blockIdx.x * BN;
    const int row0 = blockIdx.y * BM;

    const int m0 = (wid >> 2) * 32;   // 4 warps along M
    const int n0 = (wid & 3) * 32;    // 4 warps along N
    const int lrow  = lid & 15;
    const int lkoff = (lid >> 4) * 8;

    // cp.async mapping: 512 16B-chunks per part; one A chunk + one B chunk per thread.
    const int r_ = tid >> 2, c_ = tid & 3;

    const __half* pX = g_Xh + (size_t)(row0 + r_) * GK + c_ * 8;
    const __half* pW = g_Wh + (size_t)(col0 + r_) * GK + c_ * 8;

    const uint32_t dA = (uint32_t)(r_ * LDT * 2 + c_ * 16);
    const uint32_t dB = A_PART + dA;

    // ldmatrix base addresses (within a stage)
    uint32_t aA[2], bA[2];
#pragma unroll
    for (int f = 0; f < 2; f++) {
        aA[f] = smem_base + (uint32_t)((m0 + f * 16 + lrow) * LDT * 2);
        bA[f] = smem_base + A_PART + (uint32_t)((n0 + f * 16 + lrow) * LDT * 2);
    }

    float acc[2][4][4];
#pragma unroll
    for (int mf = 0; mf < 2; mf++)
#pragma unroll
        for (int nf = 0; nf < 4; nf++)
#pragma unroll
            for (int q = 0; q < 4; q++) acc[mf][nf][q] = 0.0f;

    auto issue = [&](int slot) {
        const uint32_t so = smem_base + (uint32_t)slot * STAGE_B;
        cpasync16(so + dA, pX);
        cpasync16(so + dB, pW);
        cp_commit();
        pX += KC; pW += KC;
    };

    issue(0);
    issue(1);

    int slot = 0;
    int wslot = 2;
    for (int it = 0; it < NIT; it++) {
        if (it == NIT - 1) cp_wait0(); else cp_wait1();
        __syncthreads();
        if (it + 2 < NIT) {
            issue(wslot);
            wslot = (wslot == NST - 1) ? 0 : wslot + 1;
        }

        const uint32_t sb = (uint32_t)slot * STAGE_B;
#pragma unroll
        for (int ks = 0; ks < 2; ks++) {
            const uint32_t kb = sb + (uint32_t)(ks * 16 + lkoff) * 2;
            uint32_t a[2][4];
#pragma unroll
            for (int mf = 0; mf < 2; mf++) ldmx4(a[mf], aA[mf] + kb);
            uint32_t b[4][2];
#pragma unroll
            for (int f = 0; f < 2; f++) {
                uint32_t r4[4];
                ldmx4(r4, bA[f] + kb);
                b[f * 2][0] = r4[0]; b[f * 2 + 1][0] = r4[1];
                b[f * 2][1] = r4[2]; b[f * 2 + 1][1] = r4[3];
            }
#pragma unroll
            for (int mf = 0; mf < 2; mf++)
#pragma unroll
                for (int nf = 0; nf < 4; nf++)
                    mma16816(acc[mf][nf], a[mf], b[nf]);
        }
        slot = (slot == NST - 1) ? 0 : slot + 1;
    }

    // ---- epilogue: +bias, exact GELU, store ----
    const float kInvSqrt2 = 0.70710678118654752440f;
    const int lr = lid >> 2;
    const int lc = (lid & 3) * 2;
#pragma unroll
    for (int mf = 0; mf < 2; mf++) {
#pragma unroll
        for (int nf = 0; nf < 4; nf++) {
            const int col = col0 + n0 + nf * 8 + lc;
            const float2 bv = *reinterpret_cast<const float2*>(bias + col);
            const int ra = row0 + m0 + mf * 16 + lr;
#pragma unroll
            for (int half_ = 0; half_ < 2; half_++) {
                const int r = ra + half_ * 8;
                float v0 = acc[mf][nf][half_ * 2 + 0] + bv.x;
                float v1 = acc[mf][nf][half_ * 2 + 1] + bv.y;
                float g0 = 0.5f * v0 * (1.0f + erff(v0 * kInvSqrt2));
                float g1 = 0.5f * v1 * (1.0f + erff(v1 * kInvSqrt2));
                *reinterpret_cast<float2*>(out + (size_t)r * GOUT + col) =
                    make_float2(g0, g1);
            }
        }
    }
}

extern "C" void kernel_launch(void* const* d_in, const int* in_sizes, int n_in,
                              void* d_out, int out_size) {
    // metadata order: x, adj (unused), W, b, a (unused)
    const float* X    = (const float*)d_in[0];
    const float* W    = (const float*)d_in[2];
    const float* bias = (const float*)d_in[3];
    float* out        = (float*)d_out;

    const int total4 = XN / 4 + WN / 4;
    convert_kernel<<<(total4 + 255) / 256, 256>>>(X, W);

    static bool attr_set = false;
    if (!attr_set) {
        cudaFuncSetAttribute(gemm_f16_gelu,
                             cudaFuncAttributeMaxDynamicSharedMemorySize, SMEM_B);
        attr_set = true;
    }
    dim3 grid(GOUT / BN, GN / BM);   // (4, 64) = 256 CTAs, 512 thr
    gemm_f16_gelu<<<grid, 512, SMEM_B>>>(bias, out);
}